// round 1
// baseline (speedup 1.0000x reference)
#include <cuda_runtime.h>

// Global double accumulator (no device mallocs allowed).
__device__ double g_accum;

__global__ void zero_accum_kernel() {
    g_accum = 0.0;
}

__device__ __forceinline__ float group_loss(float4 p, float4 q, float4 r) {
    // v = row[:, 1:4]  (skip .x of each float4)
    float ax = p.y, ay = p.z, az = p.w;
    float bx = q.y, by = q.z, bz = q.w;
    float cx = r.y, cy = r.z, cz = r.w;

    float ia = rsqrtf(ax * ax + ay * ay + az * az);
    float ib = rsqrtf(bx * bx + by * by + bz * bz);
    float ic = rsqrtf(cx * cx + cy * cy + cz * cz);
    ax *= ia; ay *= ia; az *= ia;
    bx *= ib; by *= ib; bz *= ib;
    cx *= ic; cy *= ic; cz *= ic;

    // G = M M^T - I (M rows = a, b, c), loss = sum(G*G)
    float daa = ax * ax + ay * ay + az * az - 1.0f;
    float dbb = bx * bx + by * by + bz * bz - 1.0f;
    float dcc = cx * cx + cy * cy + cz * cz - 1.0f;
    float dab = ax * bx + ay * by + az * bz;
    float dac = ax * cx + ay * cy + az * cz;
    float dbc = bx * cx + by * cy + bz * cz;

    return daa * daa + dbb * dbb + dcc * dcc
         + 2.0f * (dab * dab + dac * dac + dbc * dbc);
}

__global__ void __launch_bounds__(256) loss_kernel(const float4* __restrict__ in,
                                                   int nrows) {
    int idx = blockIdx.x * blockDim.x + threadIdx.x;

    float loss = 0.0f;
    if (idx < nrows) {
        const float4* row = in + (size_t)idx * 6;
        float4 r0 = row[0];
        float4 r1 = row[1];
        float4 r2 = row[2];
        float4 r3 = row[3];
        float4 r4 = row[4];
        float4 r5 = row[5];
        loss  = group_loss(r0, r1, r2);
        loss += group_loss(r3, r4, r5);
    }

    // Warp reduction
    #pragma unroll
    for (int off = 16; off > 0; off >>= 1)
        loss += __shfl_xor_sync(0xFFFFFFFFu, loss, off);

    __shared__ float warp_sums[8];
    int lane = threadIdx.x & 31;
    int warp = threadIdx.x >> 5;
    if (lane == 0) warp_sums[warp] = loss;
    __syncthreads();

    if (warp == 0) {
        loss = (lane < 8) ? warp_sums[lane] : 0.0f;
        #pragma unroll
        for (int off = 4; off > 0; off >>= 1)
            loss += __shfl_xor_sync(0xFFFFFFFFu, loss, off);
        if (lane == 0)
            atomicAdd(&g_accum, (double)loss);
    }
}

__global__ void finalize_kernel(float* out, int nrows) {
    out[0] = (float)(g_accum / (double)nrows);
}

extern "C" void kernel_launch(void* const* d_in, const int* in_sizes, int n_in,
                              void* d_out, int out_size) {
    const float4* in = (const float4*)d_in[0];
    float* out = (float*)d_out;
    int nrows = in_sizes[0] / 24;  // 24 floats per row

    zero_accum_kernel<<<1, 1>>>();

    int threads = 256;
    int blocks = (nrows + threads - 1) / threads;
    loss_kernel<<<blocks, threads>>>(in, nrows);

    finalize_kernel<<<1, 1>>>(out, nrows);
}